// round 7
// baseline (speedup 1.0000x reference)
#include <cuda_runtime.h>
#include <math.h>

// LocalHolder2D: out = sum_i w_i * log10(maxpool_k(x)), k = 3,5,7
// x: (B=8, C=64, H=256, W=256) fp32, strictly positive.
// Centered OLS weights (sum w_i = 0) -> log10(1/(H*W)) offset cancels.
//
// R6: row-per-warp (32 lanes x 8 cols = 256 = W, no halo lanes), max tree in
// signed-int domain via VIMNMX3. The 8-row ring lives in LANE-PRIVATE shared
// memory (each lane reads only the columns it wrote -> no syncs, no
// conflicts, immediate-offset addressing), cutting registers ~128 -> ~70 so
// occupancy doubles. RPB=32 so the grid supplies ~28 warps/SM.

#define HH 256
#define WW 256
#define RPB 32                 /* rows per warp-task */
#define WARPS 4
#define THREADS (WARPS * 32)
#define NEG_I ((int)0xff800000)   /* -inf bits */

static __device__ __forceinline__ int imax2(int a, int b) { return a > b ? a : b; }

// slot stride in int4 units: 32 lanes * 2 int4 = 64
static __device__ __forceinline__ void lds_row(const int4* rbase, int s, int* r) {
    int4 a = rbase[s * 64];
    int4 b = rbase[s * 64 + 1];
    r[0] = a.x; r[1] = a.y; r[2] = a.z; r[3] = a.w;
    r[4] = b.x; r[5] = b.y; r[6] = b.z; r[7] = b.w;
}

static __device__ __forceinline__ void ld_gmem_row(const int* src, int row,
                                                   bool valid, int4& a, int4& b) {
    if (valid) {
        const int4* p = (const int4*)(src + row * WW);
        a = p[0]; b = p[1];
    } else {
        a = make_int4(NEG_I, NEG_I, NEG_I, NEG_I);
        b = a;
    }
}

__global__ __launch_bounds__(THREADS, 7)
void holder_kernel(const int* __restrict__ x, float* __restrict__ out,
                   float w3, float w5, float w7)
{
    // ring[warp][slot][lane][2 x int4]  : 4*8*32*2*16 = 32 KB
    __shared__ int4 ring[WARPS][8][32][2];

    const int lane = threadIdx.x & 31;
    const int warp = threadIdx.x >> 5;
    const int task = blockIdx.x * WARPS + warp;      // 4096 tasks
    const int plane = task >> 3;
    const int y0 = (task & 7) * RPB;                 // multiple of 8

    const int* __restrict__ src = x   + (size_t)plane * (HH * WW) + lane * 8;
    float*     __restrict__ dst = out + (size_t)plane * (HH * WW) + lane * 8;

    int4* rbase = &ring[warp][0][lane][0];

    const unsigned FULL = 0xffffffffu;
    const bool l0 = (lane == 0), l31 = (lane == 31);

    // Prologue: rows y0-3 .. y0+3 -> slot (row & 7) = (j+5)&7.
    #pragma unroll
    for (int j = 0; j < 7; ++j) {
        const int row = y0 - 3 + j;
        const int s = (j + 5) & 7;
        int4 a, b;
        ld_gmem_row(src, row, row >= 0, a, b);
        rbase[s * 64]     = a;
        rbase[s * 64 + 1] = b;
    }

    for (int ib = 0; ib < RPB; ib += 8) {
        #pragma unroll
        for (int u = 0; u < 8; ++u) {
            const int y = y0 + ib + u;            // output row; y & 7 == u
            // Prefetch row y+4 into slot (u+4)&7.
            {
                int4 a, b;
                ld_gmem_row(src, y + 4, (y + 4) < HH, a, b);
                const int s = (u + 4) & 7;
                rbase[s * 64]     = a;
                rbase[s * 64 + 1] = b;
            }

            int ra[8], rb[8], rc[8];
            int v[8];
            float acc[8];

            // ---- vertical k=3: rows y-1, y, y+1 ----
            lds_row(rbase,  u,          ra);   // y
            lds_row(rbase, (u + 7) & 7, rb);   // y-1
            lds_row(rbase, (u + 1) & 7, rc);   // y+1
            #pragma unroll
            for (int j = 0; j < 8; ++j)
                v[j] = __vimax3_s32(rb[j], ra[j], rc[j]);

            // ---- horizontal k=3 ----
            {
                int L = __shfl_up_sync  (FULL, v[7], 1); if (l0)  L = NEG_I;
                int R = __shfl_down_sync(FULL, v[0], 1); if (l31) R = NEG_I;
                acc[0] = w3 * __log2f(__int_as_float(__vimax3_s32(L, v[0], v[1])));
                #pragma unroll
                for (int j = 1; j < 7; ++j)
                    acc[j] = w3 * __log2f(__int_as_float(
                                 __vimax3_s32(v[j - 1], v[j], v[j + 1])));
                acc[7] = w3 * __log2f(__int_as_float(__vimax3_s32(v[6], v[7], R)));
            }

            // ---- vertical k=5: add rows y-2, y+2 ----
            lds_row(rbase, (u + 6) & 7, ra);   // y-2
            lds_row(rbase, (u + 2) & 7, rb);   // y+2
            #pragma unroll
            for (int j = 0; j < 8; ++j)
                v[j] = __vimax3_s32(v[j], ra[j], rb[j]);

            // ---- horizontal k=5 ----
            {
                int p01 = imax2(v[0], v[1]), p23 = imax2(v[2], v[3]);
                int p45 = imax2(v[4], v[5]), p67 = imax2(v[6], v[7]);
                int Lp = __shfl_up_sync  (FULL, p67, 1);
                int L7 = __shfl_up_sync  (FULL, v[7], 1);
                int R0 = __shfl_down_sync(FULL, v[0], 1);
                int Rp = __shfl_down_sync(FULL, p01, 1);
                if (l0)  { Lp = NEG_I; L7 = NEG_I; }
                if (l31) { R0 = NEG_I; Rp = NEG_I; }
                int m[8];
                m[0] = __vimax3_s32(Lp,  p01, v[2]);
                m[1] = __vimax3_s32(L7,  p01, p23);
                m[2] = __vimax3_s32(p01, p23, v[4]);
                m[3] = __vimax3_s32(v[1], p23, p45);
                m[4] = __vimax3_s32(p23, p45, v[6]);
                m[5] = __vimax3_s32(v[3], p45, p67);
                m[6] = __vimax3_s32(p45, p67, R0);
                m[7] = __vimax3_s32(v[5], p67, Rp);
                #pragma unroll
                for (int j = 0; j < 8; ++j)
                    acc[j] = fmaf(w5, __log2f(__int_as_float(m[j])), acc[j]);
            }

            // ---- vertical k=7: add rows y-3, y+3 ----
            lds_row(rbase, (u + 5) & 7, ra);   // y-3
            lds_row(rbase, (u + 3) & 7, rb);   // y+3
            #pragma unroll
            for (int j = 0; j < 8; ++j)
                v[j] = __vimax3_s32(v[j], ra[j], rb[j]);

            // ---- horizontal k=7 ----
            {
                int p01 = imax2(v[0], v[1]), p23 = imax2(v[2], v[3]);
                int p45 = imax2(v[4], v[5]), p67 = imax2(v[6], v[7]);
                int a03 = imax2(p01, p23),   a47 = imax2(p45, p67);
                int suf3 = imax2(v[5], p67); // cols 5..7
                int pre3 = imax2(p01, v[2]); // cols 0..2
                int Ls  = __shfl_up_sync  (FULL, suf3, 1);
                int Lq  = __shfl_up_sync  (FULL, p67, 1);
                int L7v = __shfl_up_sync  (FULL, v[7], 1);
                int R0v = __shfl_down_sync(FULL, v[0], 1);
                int Rq  = __shfl_down_sync(FULL, p01, 1);
                int Rp3 = __shfl_down_sync(FULL, pre3, 1);
                if (l0)  { Ls = NEG_I; Lq = NEG_I; L7v = NEG_I; }
                if (l31) { R0v = NEG_I; Rq = NEG_I; Rp3 = NEG_I; }
                int m[8];
                m[0] = imax2(Ls, a03);               // -3..3
                m[1] = __vimax3_s32(Lq,  a03, v[4]); // -2..4
                m[2] = __vimax3_s32(L7v, a03, p45);  // -1..5
                m[3] = __vimax3_s32(a03, p45, v[6]); //  0..6
                m[4] = __vimax3_s32(v[1], p23, a47); //  1..7
                m[5] = __vimax3_s32(p23, a47, R0v);  //  2..8
                m[6] = __vimax3_s32(v[3], a47, Rq);  //  3..9
                m[7] = imax2(a47, Rp3);              //  4..10
                #pragma unroll
                for (int j = 0; j < 8; ++j)
                    acc[j] = fmaf(w7, __log2f(__int_as_float(m[j])), acc[j]);
            }

            float* dp = dst + y * WW;
            ((float4*)dp)[0] = make_float4(acc[0], acc[1], acc[2], acc[3]);
            ((float4*)dp)[1] = make_float4(acc[4], acc[5], acc[6], acc[7]);
        }
    }
}

extern "C" void kernel_launch(void* const* d_in, const int* in_sizes, int n_in,
                              void* d_out, int out_size)
{
    const int* x = (const int*)d_in[0];
    float* out = (float*)d_out;

    const int planes = in_sizes[0] / (HH * WW);      // 512

    // Closed-form OLS slope weights (double on host); fold in log10(2).
    double l3 = log10(3.0), l5 = log10(5.0), l7 = log10(7.0);
    double mean = (l3 + l5 + l7) / 3.0;
    double c3 = l3 - mean, c5 = l5 - mean, c7 = l7 - mean;
    double s = c3 * c3 + c5 * c5 + c7 * c7;
    double L10_2 = 0.30102999566398119521;
    float w3 = (float)((c3 / s) * L10_2);
    float w5 = (float)((c5 / s) * L10_2);
    float w7 = (float)((c7 / s) * L10_2);

    const int tasks = planes * (HH / RPB);           // 4096
    dim3 grid(tasks / WARPS);                        // 1024 blocks
    dim3 block(THREADS);
    holder_kernel<<<grid, block>>>(x, out, w3, w5, w7);
}

// round 9
// speedup vs baseline: 1.6106x; 1.6106x over previous
#include <cuda_runtime.h>
#include <math.h>

// LocalHolder2D: out = sum_i w_i * log10(maxpool_k(x)), k = 3,5,7
// x: (B=8, C=64, H=256, W=256) fp32, strictly positive.
// Centered OLS weights (sum w_i = 0) -> log10(1/(H*W)) offset cancels.
//
// R8 = R5 (register ring, row-per-warp) + occupancy fixes:
//  - one full row per warp: 32 lanes x 8 cols = 256 = W, no halo lanes;
//    image edges are -inf via SEL on lanes 0/31.
//  - max tree in signed-int domain (positive floats + -inf monotone under
//    signed compare) with 3-input VIMNMX3.
//  - register ring of 8 rows x 8 cols (slot = row & 7), prefetch +4 rows.
//  - RPB=32 -> 4096 warp-tasks (27.7 warps/SM supplied).
//  - __launch_bounds__(128,5) -> reg cap 102, ~20 warps/SM capacity.

#define HH 256
#define WW 256
#define RPB 32                 /* rows per warp-task */
#define WARPS 4
#define THREADS (WARPS * 32)
#define NEG_I ((int)0xff800000)   /* -inf bits */

static __device__ __forceinline__ int imax2(int a, int b) { return a > b ? a : b; }

__global__ __launch_bounds__(THREADS, 5)
void holder_kernel(const int* __restrict__ x, float* __restrict__ out,
                   float w3, float w5, float w7)
{
    const int lane = threadIdx.x & 31;
    const int warp = threadIdx.x >> 5;
    const int task = blockIdx.x * WARPS + warp;     // 4096 tasks
    const int plane = task >> 3;
    const int y0 = (task & 7) * RPB;                // multiple of 8

    const int* __restrict__ src = x   + (size_t)plane * (HH * WW) + lane * 8;
    float*     __restrict__ dst = out + (size_t)plane * (HH * WW) + lane * 8;

    const unsigned FULL = 0xffffffffu;
    const bool l0 = (lane == 0), l31 = (lane == 31);

    // ring[slot][col]; slot for row r is r & 7 (y0 % 8 == 0).
    int ring[8][8];

    // Prologue: rows y0-3 .. y0+3 -> slots (j+5)&7 for j=0..6.
    #pragma unroll
    for (int j = 0; j < 7; ++j) {
        const int row = y0 - 3 + j;
        const int s = (j + 5) & 7;
        if (row >= 0) {
            const int4* rp = (const int4*)(src + row * WW);
            int4 a = rp[0], b = rp[1];
            ring[s][0] = a.x; ring[s][1] = a.y; ring[s][2] = a.z; ring[s][3] = a.w;
            ring[s][4] = b.x; ring[s][5] = b.y; ring[s][6] = b.z; ring[s][7] = b.w;
        } else {
            #pragma unroll
            for (int t = 0; t < 8; ++t) ring[s][t] = NEG_I;
        }
    }

    for (int ib = 0; ib < RPB; ib += 8) {
        #pragma unroll
        for (int u = 0; u < 8; ++u) {
            const int y = y0 + ib + u;            // output row; y & 7 == u
            // Prefetch row y+4 into slot (u+4)&7 (vacated row y-4).
            {
                const int row = y + 4;
                const int s = (u + 4) & 7;
                if (row < HH) {
                    const int4* rp = (const int4*)(src + row * WW);
                    int4 a = rp[0], b = rp[1];
                    ring[s][0] = a.x; ring[s][1] = a.y; ring[s][2] = a.z; ring[s][3] = a.w;
                    ring[s][4] = b.x; ring[s][5] = b.y; ring[s][6] = b.z; ring[s][7] = b.w;
                } else {
                    #pragma unroll
                    for (int t = 0; t < 8; ++t) ring[s][t] = NEG_I;
                }
            }

            int v[8];
            float acc[8];

            // ---- k = 3 ----
            #pragma unroll
            for (int j = 0; j < 8; ++j)
                v[j] = __vimax3_s32(ring[(u + 7) & 7][j], ring[u][j],
                                    ring[(u + 1) & 7][j]);
            {
                int L = __shfl_up_sync  (FULL, v[7], 1); if (l0)  L = NEG_I;
                int R = __shfl_down_sync(FULL, v[0], 1); if (l31) R = NEG_I;
                int m0 = __vimax3_s32(L, v[0], v[1]);
                int m7 = __vimax3_s32(v[6], v[7], R);
                acc[0] = w3 * __log2f(__int_as_float(m0));
                #pragma unroll
                for (int j = 1; j < 7; ++j)
                    acc[j] = w3 * __log2f(__int_as_float(
                                 __vimax3_s32(v[j - 1], v[j], v[j + 1])));
                acc[7] = w3 * __log2f(__int_as_float(m7));
            }

            // ---- k = 5 ----
            #pragma unroll
            for (int j = 0; j < 8; ++j)
                v[j] = __vimax3_s32(v[j], ring[(u + 6) & 7][j],
                                    ring[(u + 2) & 7][j]);
            {
                int p01 = imax2(v[0], v[1]), p23 = imax2(v[2], v[3]);
                int p45 = imax2(v[4], v[5]), p67 = imax2(v[6], v[7]);
                int Lp = __shfl_up_sync  (FULL, p67, 1);
                int L7 = __shfl_up_sync  (FULL, v[7], 1);
                int R0 = __shfl_down_sync(FULL, v[0], 1);
                int Rp = __shfl_down_sync(FULL, p01, 1);
                if (l0)  { Lp = NEG_I; L7 = NEG_I; }
                if (l31) { R0 = NEG_I; Rp = NEG_I; }
                int m[8];
                m[0] = __vimax3_s32(Lp,  p01, v[2]);
                m[1] = __vimax3_s32(L7,  p01, p23);
                m[2] = __vimax3_s32(p01, p23, v[4]);
                m[3] = __vimax3_s32(v[1], p23, p45);
                m[4] = __vimax3_s32(p23, p45, v[6]);
                m[5] = __vimax3_s32(v[3], p45, p67);
                m[6] = __vimax3_s32(p45, p67, R0);
                m[7] = __vimax3_s32(v[5], p67, Rp);
                #pragma unroll
                for (int j = 0; j < 8; ++j)
                    acc[j] = fmaf(w5, __log2f(__int_as_float(m[j])), acc[j]);
            }

            // ---- k = 7 ----
            #pragma unroll
            for (int j = 0; j < 8; ++j)
                v[j] = __vimax3_s32(v[j], ring[(u + 5) & 7][j],
                                    ring[(u + 3) & 7][j]);
            {
                int p01 = imax2(v[0], v[1]), p23 = imax2(v[2], v[3]);
                int p45 = imax2(v[4], v[5]), p67 = imax2(v[6], v[7]);
                int a03 = imax2(p01, p23),   a47 = imax2(p45, p67);
                int suf3 = imax2(v[5], p67); // cols 5..7
                int pre3 = imax2(p01, v[2]); // cols 0..2
                int Ls  = __shfl_up_sync  (FULL, suf3, 1);
                int Lq  = __shfl_up_sync  (FULL, p67, 1);
                int L7v = __shfl_up_sync  (FULL, v[7], 1);
                int R0v = __shfl_down_sync(FULL, v[0], 1);
                int Rq  = __shfl_down_sync(FULL, p01, 1);
                int Rp3 = __shfl_down_sync(FULL, pre3, 1);
                if (l0)  { Ls = NEG_I; Lq = NEG_I; L7v = NEG_I; }
                if (l31) { R0v = NEG_I; Rq = NEG_I; Rp3 = NEG_I; }
                int m[8];
                m[0] = imax2(Ls, a03);               // -3..3
                m[1] = __vimax3_s32(Lq,  a03, v[4]); // -2..4
                m[2] = __vimax3_s32(L7v, a03, p45);  // -1..5
                m[3] = __vimax3_s32(a03, p45, v[6]); //  0..6
                m[4] = __vimax3_s32(v[1], p23, a47); //  1..7
                m[5] = __vimax3_s32(p23, a47, R0v);  //  2..8
                m[6] = __vimax3_s32(v[3], a47, Rq);  //  3..9
                m[7] = imax2(a47, Rp3);              //  4..10
                #pragma unroll
                for (int j = 0; j < 8; ++j)
                    acc[j] = fmaf(w7, __log2f(__int_as_float(m[j])), acc[j]);
            }

            float* dp = dst + y * WW;
            ((float4*)dp)[0] = make_float4(acc[0], acc[1], acc[2], acc[3]);
            ((float4*)dp)[1] = make_float4(acc[4], acc[5], acc[6], acc[7]);
        }
    }
}

extern "C" void kernel_launch(void* const* d_in, const int* in_sizes, int n_in,
                              void* d_out, int out_size)
{
    const int* x = (const int*)d_in[0];
    float* out = (float*)d_out;

    const int planes = in_sizes[0] / (HH * WW);     // 512

    // Closed-form OLS slope weights (double on host); fold in log10(2).
    double l3 = log10(3.0), l5 = log10(5.0), l7 = log10(7.0);
    double mean = (l3 + l5 + l7) / 3.0;
    double c3 = l3 - mean, c5 = l5 - mean, c7 = l7 - mean;
    double s = c3 * c3 + c5 * c5 + c7 * c7;
    double L10_2 = 0.30102999566398119521;
    float w3 = (float)((c3 / s) * L10_2);
    float w5 = (float)((c5 / s) * L10_2);
    float w7 = (float)((c7 / s) * L10_2);

    const int tasks = planes * (HH / RPB);          // 4096
    dim3 grid(tasks / WARPS);                       // 1024 blocks
    dim3 block(THREADS);
    holder_kernel<<<grid, block>>>(x, out, w3, w5, w7);
}

// round 10
// speedup vs baseline: 2.1753x; 1.3506x over previous
#include <cuda_runtime.h>
#include <math.h>

// LocalHolder2D: out = sum_i w_i * log10(maxpool_k(x)), k = 3,5,7
// x: (B=8, C=64, H=256, W=256) fp32, strictly positive.
// Centered OLS weights (sum w_i = 0) -> log10(1/(H*W)) offset cancels.
//
// R10 = R5 inner loop EXACTLY (128-reg schedule, register ring, row-per-warp,
// VIMNMX3 int-domain max tree, 12 shuffles/row) with only the task geometry
// changed: RPB 64 -> 32 so the grid supplies 4096 warp-tasks (27.7 warps/SM)
// instead of 2048 (13.8), letting occupancy reach the 16-warp/SM register cap.
// launch_bounds stays (128,4): do NOT squeeze registers (R8 showed 96-reg
// rescheduling costs more than the occupancy it buys).

#define HH 256
#define WW 256
#define RPB 32                 /* rows per warp-task */
#define WARPS 4
#define THREADS (WARPS * 32)
#define NEG_I ((int)0xff800000)   /* -inf bits */

static __device__ __forceinline__ int imax2(int a, int b) { return a > b ? a : b; }

__global__ __launch_bounds__(THREADS, 4)
void holder_kernel(const int* __restrict__ x, float* __restrict__ out,
                   float w3, float w5, float w7)
{
    const int lane = threadIdx.x & 31;
    const int warp = threadIdx.x >> 5;
    const int task = blockIdx.x * WARPS + warp;     // 4096 tasks
    const int plane = task >> 3;
    const int y0 = (task & 7) * RPB;                // multiple of 8

    const int* __restrict__ src = x   + (size_t)plane * (HH * WW) + lane * 8;
    float*     __restrict__ dst = out + (size_t)plane * (HH * WW) + lane * 8;

    const unsigned FULL = 0xffffffffu;
    const bool l0 = (lane == 0), l31 = (lane == 31);

    // ring[slot][col]; slot for row r is r & 7 (y0 % 8 == 0).
    int ring[8][8];

    // Prologue: rows y0-3 .. y0+3 -> slots (j+5)&7 for j=0..6.
    #pragma unroll
    for (int j = 0; j < 7; ++j) {
        const int row = y0 - 3 + j;
        const int s = (j + 5) & 7;
        if (row >= 0) {
            const int4* rp = (const int4*)(src + row * WW);
            int4 a = rp[0], b = rp[1];
            ring[s][0] = a.x; ring[s][1] = a.y; ring[s][2] = a.z; ring[s][3] = a.w;
            ring[s][4] = b.x; ring[s][5] = b.y; ring[s][6] = b.z; ring[s][7] = b.w;
        } else {
            #pragma unroll
            for (int t = 0; t < 8; ++t) ring[s][t] = NEG_I;
        }
    }

    for (int ib = 0; ib < RPB; ib += 8) {
        #pragma unroll
        for (int u = 0; u < 8; ++u) {
            const int y = y0 + ib + u;            // output row; y & 7 == u
            // Prefetch row y+4 into slot (u+4)&7 (vacated row y-4).
            {
                const int row = y + 4;
                const int s = (u + 4) & 7;
                if (row < HH) {
                    const int4* rp = (const int4*)(src + row * WW);
                    int4 a = rp[0], b = rp[1];
                    ring[s][0] = a.x; ring[s][1] = a.y; ring[s][2] = a.z; ring[s][3] = a.w;
                    ring[s][4] = b.x; ring[s][5] = b.y; ring[s][6] = b.z; ring[s][7] = b.w;
                } else {
                    #pragma unroll
                    for (int t = 0; t < 8; ++t) ring[s][t] = NEG_I;
                }
            }

            int v[8];
            float acc[8];

            // ---- k = 3 ----
            #pragma unroll
            for (int j = 0; j < 8; ++j)
                v[j] = __vimax3_s32(ring[(u + 7) & 7][j], ring[u][j],
                                    ring[(u + 1) & 7][j]);
            {
                int L = __shfl_up_sync  (FULL, v[7], 1); if (l0)  L = NEG_I;
                int R = __shfl_down_sync(FULL, v[0], 1); if (l31) R = NEG_I;
                int m0 = __vimax3_s32(L, v[0], v[1]);
                int m7 = __vimax3_s32(v[6], v[7], R);
                acc[0] = w3 * __log2f(__int_as_float(m0));
                #pragma unroll
                for (int j = 1; j < 7; ++j)
                    acc[j] = w3 * __log2f(__int_as_float(
                                 __vimax3_s32(v[j - 1], v[j], v[j + 1])));
                acc[7] = w3 * __log2f(__int_as_float(m7));
            }

            // ---- k = 5 ----
            #pragma unroll
            for (int j = 0; j < 8; ++j)
                v[j] = __vimax3_s32(v[j], ring[(u + 6) & 7][j],
                                    ring[(u + 2) & 7][j]);
            {
                int p01 = imax2(v[0], v[1]), p23 = imax2(v[2], v[3]);
                int p45 = imax2(v[4], v[5]), p67 = imax2(v[6], v[7]);
                int Lp = __shfl_up_sync  (FULL, p67, 1);
                int L7 = __shfl_up_sync  (FULL, v[7], 1);
                int R0 = __shfl_down_sync(FULL, v[0], 1);
                int Rp = __shfl_down_sync(FULL, p01, 1);
                if (l0)  { Lp = NEG_I; L7 = NEG_I; }
                if (l31) { R0 = NEG_I; Rp = NEG_I; }
                int m[8];
                m[0] = __vimax3_s32(Lp,  p01, v[2]);
                m[1] = __vimax3_s32(L7,  p01, p23);
                m[2] = __vimax3_s32(p01, p23, v[4]);
                m[3] = __vimax3_s32(v[1], p23, p45);
                m[4] = __vimax3_s32(p23, p45, v[6]);
                m[5] = __vimax3_s32(v[3], p45, p67);
                m[6] = __vimax3_s32(p45, p67, R0);
                m[7] = __vimax3_s32(v[5], p67, Rp);
                #pragma unroll
                for (int j = 0; j < 8; ++j)
                    acc[j] = fmaf(w5, __log2f(__int_as_float(m[j])), acc[j]);
            }

            // ---- k = 7 ----
            #pragma unroll
            for (int j = 0; j < 8; ++j)
                v[j] = __vimax3_s32(v[j], ring[(u + 5) & 7][j],
                                    ring[(u + 3) & 7][j]);
            {
                int p01 = imax2(v[0], v[1]), p23 = imax2(v[2], v[3]);
                int p45 = imax2(v[4], v[5]), p67 = imax2(v[6], v[7]);
                int a03 = imax2(p01, p23),   a47 = imax2(p45, p67);
                int suf3 = imax2(v[5], p67); // cols 5..7
                int pre3 = imax2(p01, v[2]); // cols 0..2
                int Ls  = __shfl_up_sync  (FULL, suf3, 1);
                int Lq  = __shfl_up_sync  (FULL, p67, 1);
                int L7v = __shfl_up_sync  (FULL, v[7], 1);
                int R0v = __shfl_down_sync(FULL, v[0], 1);
                int Rq  = __shfl_down_sync(FULL, p01, 1);
                int Rp3 = __shfl_down_sync(FULL, pre3, 1);
                if (l0)  { Ls = NEG_I; Lq = NEG_I; L7v = NEG_I; }
                if (l31) { R0v = NEG_I; Rq = NEG_I; Rp3 = NEG_I; }
                int m[8];
                m[0] = imax2(Ls, a03);               // -3..3
                m[1] = __vimax3_s32(Lq,  a03, v[4]); // -2..4
                m[2] = __vimax3_s32(L7v, a03, p45);  // -1..5
                m[3] = __vimax3_s32(a03, p45, v[6]); //  0..6
                m[4] = __vimax3_s32(v[1], p23, a47); //  1..7
                m[5] = __vimax3_s32(p23, a47, R0v);  //  2..8
                m[6] = __vimax3_s32(v[3], a47, Rq);  //  3..9
                m[7] = imax2(a47, Rp3);              //  4..10
                #pragma unroll
                for (int j = 0; j < 8; ++j)
                    acc[j] = fmaf(w7, __log2f(__int_as_float(m[j])), acc[j]);
            }

            float* dp = dst + y * WW;
            ((float4*)dp)[0] = make_float4(acc[0], acc[1], acc[2], acc[3]);
            ((float4*)dp)[1] = make_float4(acc[4], acc[5], acc[6], acc[7]);
        }
    }
}

extern "C" void kernel_launch(void* const* d_in, const int* in_sizes, int n_in,
                              void* d_out, int out_size)
{
    const int* x = (const int*)d_in[0];
    float* out = (float*)d_out;

    const int planes = in_sizes[0] / (HH * WW);     // 512

    // Closed-form OLS slope weights (double on host); fold in log10(2).
    double l3 = log10(3.0), l5 = log10(5.0), l7 = log10(7.0);
    double mean = (l3 + l5 + l7) / 3.0;
    double c3 = l3 - mean, c5 = l5 - mean, c7 = l7 - mean;
    double s = c3 * c3 + c5 * c5 + c7 * c7;
    double L10_2 = 0.30102999566398119521;
    float w3 = (float)((c3 / s) * L10_2);
    float w5 = (float)((c5 / s) * L10_2);
    float w7 = (float)((c7 / s) * L10_2);

    const int tasks = planes * (HH / RPB);          // 4096
    dim3 grid(tasks / WARPS);                       // 1024 blocks
    dim3 block(THREADS);
    holder_kernel<<<grid, block>>>(x, out, w3, w5, w7);
}